// round 7
// baseline (speedup 1.0000x reference)
#include <cuda_runtime.h>
#include <cuda_bf16.h>
#include <cstdint>
#include <math.h>

// Problem constants
#define Bsz 2
#define Tsz 2048
#define NE 2048
#define NH 16
#define NKV 4
#define DH 128
#define GQ 4
#define QKV_W 3072          // NE + 2*NKV*DH
#define MROWS (Bsz*Tsz)     // 4096

// Scratch (allocation-free rule: __device__ globals)
__device__ float g_qkv[MROWS * QKV_W];                 // ~50 MB
__device__ float g_y[MROWS * NE];                      // ~34 MB
__device__ __nv_bfloat16 g_ahi[MROWS * NE];            // activations hi
__device__ __nv_bfloat16 g_alo[MROWS * NE];            // activations lo
__device__ __nv_bfloat16 g_bhi[QKV_W * NE];            // weight^T hi  [N,K]
__device__ __nv_bfloat16 g_blo[QKV_W * NE];            // weight^T lo  [N,K]

// ---------------------------------------------------------------------------
// Helpers
// ---------------------------------------------------------------------------
__device__ __forceinline__ uint32_t smem_u32(const void* p) {
    uint32_t a;
    asm("{ .reg .u64 t; cvta.to.shared.u64 t, %1; cvt.u32.u64 %0, t; }" : "=r"(a) : "l"(p));
    return a;
}
__device__ __forceinline__ void cpa16(uint32_t dst, const void* src) {
    asm volatile("cp.async.cg.shared.global [%0], [%1], 16;" :: "r"(dst), "l"(src));
}
#define CP_COMMIT() asm volatile("cp.async.commit_group;" ::: "memory")
#define CP_WAIT0()  asm volatile("cp.async.wait_group 0;" ::: "memory")
#define CP_WAIT1()  asm volatile("cp.async.wait_group 1;" ::: "memory")

#define LDSM4(r0, r1, r2, r3, addr) \
    asm volatile("ldmatrix.sync.aligned.m8n8.x4.shared.b16 {%0,%1,%2,%3}, [%4];" \
        : "=r"(r0), "=r"(r1), "=r"(r2), "=r"(r3) : "r"(addr))

__device__ __forceinline__ void mma16816(float* d, const uint32_t* a, const uint32_t* b) {
    asm volatile(
        "mma.sync.aligned.m16n8k16.row.col.f32.bf16.bf16.f32 "
        "{%0,%1,%2,%3}, {%4,%5,%6,%7}, {%8,%9}, {%0,%1,%2,%3};"
        : "+f"(d[0]), "+f"(d[1]), "+f"(d[2]), "+f"(d[3])
        : "r"(a[0]), "r"(a[1]), "r"(a[2]), "r"(a[3]), "r"(b[0]), "r"(b[1]));
}

// ---------------------------------------------------------------------------
// Split fp32 -> (hi, lo) bf16, same layout.
// ---------------------------------------------------------------------------
__global__ void split_kernel(const float* __restrict__ X,
                             __nv_bfloat16* __restrict__ hi,
                             __nv_bfloat16* __restrict__ lo, int n) {
    int i = blockIdx.x * blockDim.x + threadIdx.x;
    if (i >= n) return;
    float v = X[i];
    __nv_bfloat16 h = __float2bfloat16(v);
    float r = v - __bfloat162float(h);
    hi[i] = h;
    lo[i] = __float2bfloat16(r);
}

// ---------------------------------------------------------------------------
// Split + transpose: W [K, N] fp32 -> hi/lo bf16 [N, K]
// ---------------------------------------------------------------------------
__global__ void split_T_kernel(const float* __restrict__ W,
                               __nv_bfloat16* __restrict__ hi,
                               __nv_bfloat16* __restrict__ lo, int K, int N) {
    __shared__ float t[32][33];
    const int bx = blockIdx.x * 32;   // N tile
    const int by = blockIdx.y * 32;   // K tile
    const int tx = threadIdx.x;       // 0..31
    const int ty0 = threadIdx.y;      // 0..7
    #pragma unroll
    for (int i = 0; i < 4; i++) {
        int ty = ty0 + i * 8;
        t[ty][tx] = W[(size_t)(by + ty) * N + bx + tx];
    }
    __syncthreads();
    #pragma unroll
    for (int i = 0; i < 4; i++) {
        int ty = ty0 + i * 8;
        float v = t[tx][ty];                  // = W[by+tx][bx+ty]
        __nv_bfloat16 h = __float2bfloat16(v);
        float r = v - __bfloat162float(h);
        size_t o = (size_t)(bx + ty) * K + by + tx;   // out[n][k]
        hi[o] = h;
        lo[o] = __float2bfloat16(r);
    }
}

// ---------------------------------------------------------------------------
// mma.sync split-bf16 GEMM: C[M,N] = A[M,K] @ Bt[N,K]^T  (fp32 out)
// ---------------------------------------------------------------------------
#define BM 128
#define BN 128
#define BKC 32
#define PITCH 40                       // halfs per smem row (80 B)
#define PART_H (128 * PITCH)           // 5120 halfs per part
#define BUF_H (4 * PART_H)             // 20480 halfs per buffer
#define OFF_AHI 0
#define OFF_ALO PART_H
#define OFF_BHI (2 * PART_H)
#define OFF_BLO (3 * PART_H)
#define GEMM_SMEM_BYTES (2 * BUF_H * 2)   // 81920

__global__ __launch_bounds__(256)
void bgemm_mma(const __nv_bfloat16* __restrict__ Ahi, const __nv_bfloat16* __restrict__ Alo,
               const __nv_bfloat16* __restrict__ Bhi, const __nv_bfloat16* __restrict__ Blo,
               float* __restrict__ C, int N, int K) {
    extern __shared__ __nv_bfloat16 sm[];
    const uint32_t sbase = smem_u32(sm);
    const int tid = threadIdx.x;
    const int wid = tid >> 5;
    const int lid = tid & 31;
    const int wm = wid >> 1;           // 0..3 -> 32-row slab
    const int wn = wid & 1;            // 0..1 -> 64-col slab
    const int bm = blockIdx.y * BM;
    const int bn = blockIdx.x * BN;

    const int nch = K / BKC;

    const __nv_bfloat16* gAh = Ahi + (size_t)bm * K;
    const __nv_bfloat16* gAl = Alo + (size_t)bm * K;
    const __nv_bfloat16* gBh = Bhi + (size_t)bn * K;
    const __nv_bfloat16* gBl = Blo + (size_t)bn * K;

    const int l_row0 = tid >> 2;            // 0..63
    const int l_seg  = tid & 3;             // 0..3

    float acc[2][8][4];
    #pragma unroll
    for (int mt = 0; mt < 2; mt++)
        #pragma unroll
        for (int nt = 0; nt < 8; nt++)
            #pragma unroll
            for (int i = 0; i < 4; i++) acc[mt][nt][i] = 0.f;

    const int mi = lid >> 3;
    const int mr = lid & 7;
    const int a_row = wm * 32 + (mi & 1) * 8 + mr;
    const int a_kof = (mi >> 1) * 8;
    const int b_row = wn * 64 + (mi >> 1) * 8 + mr;
    const int b_kof = (mi & 1) * 8;

    // prologue load chunk 0
    {
        const uint32_t sb = sbase;
        #pragma unroll
        for (int it = 0; it < 2; it++) {
            int row = l_row0 + it * 64;
            uint32_t so = (uint32_t)(row * PITCH + l_seg * 8) * 2;
            size_t go = (size_t)row * K + l_seg * 8;
            cpa16(sb + OFF_AHI * 2 + so, gAh + go);
            cpa16(sb + OFF_ALO * 2 + so, gAl + go);
            cpa16(sb + OFF_BHI * 2 + so, gBh + go);
            cpa16(sb + OFF_BLO * 2 + so, gBl + go);
        }
        CP_COMMIT();
    }

    for (int ch = 0; ch < nch; ch++) {
        if (ch + 1 < nch) {
            const int kof = (ch + 1) * BKC;
            const uint32_t sb = sbase + (uint32_t)((ch + 1) & 1) * (BUF_H * 2);
            #pragma unroll
            for (int it = 0; it < 2; it++) {
                int row = l_row0 + it * 64;
                uint32_t so = (uint32_t)(row * PITCH + l_seg * 8) * 2;
                size_t go = (size_t)row * K + kof + l_seg * 8;
                cpa16(sb + OFF_AHI * 2 + so, gAh + go);
                cpa16(sb + OFF_ALO * 2 + so, gAl + go);
                cpa16(sb + OFF_BHI * 2 + so, gBh + go);
                cpa16(sb + OFF_BLO * 2 + so, gBl + go);
            }
            CP_COMMIT();
            CP_WAIT1();
        } else {
            CP_WAIT0();
        }
        __syncthreads();

        const uint32_t sb = sbase + (uint32_t)(ch & 1) * (BUF_H * 2);

        #pragma unroll
        for (int ks = 0; ks < 2; ks++) {
            const int kb = ks * 16;
            uint32_t bh[16], bl[16];
            #pragma unroll
            for (int g = 0; g < 4; g++) {
                uint32_t ba = sb + (uint32_t)((b_row + g * 16) * PITCH + kb + b_kof) * 2;
                LDSM4(bh[g * 4 + 0], bh[g * 4 + 1], bh[g * 4 + 2], bh[g * 4 + 3], ba + OFF_BHI * 2);
                LDSM4(bl[g * 4 + 0], bl[g * 4 + 1], bl[g * 4 + 2], bl[g * 4 + 3], ba + OFF_BLO * 2);
            }
            #pragma unroll
            for (int mt = 0; mt < 2; mt++) {
                uint32_t ah[4], al[4];
                uint32_t aa = sb + (uint32_t)((a_row + mt * 16) * PITCH + kb + a_kof) * 2;
                LDSM4(ah[0], ah[1], ah[2], ah[3], aa + OFF_AHI * 2);
                LDSM4(al[0], al[1], al[2], al[3], aa + OFF_ALO * 2);
                #pragma unroll
                for (int nt = 0; nt < 8; nt++) {
                    mma16816(acc[mt][nt], ah, &bh[nt * 2]);
                    mma16816(acc[mt][nt], al, &bh[nt * 2]);
                    mma16816(acc[mt][nt], ah, &bl[nt * 2]);
                }
            }
        }
        __syncthreads();
    }

    const int er = lid >> 2;
    const int ec = (lid & 3) * 2;
    #pragma unroll
    for (int mt = 0; mt < 2; mt++) {
        #pragma unroll
        for (int nt = 0; nt < 8; nt++) {
            int r0 = bm + wm * 32 + mt * 16 + er;
            int c0 = bn + wn * 64 + nt * 8 + ec;
            *(float2*)&C[(size_t)r0 * N + c0]       = make_float2(acc[mt][nt][0], acc[mt][nt][1]);
            *(float2*)&C[(size_t)(r0 + 8) * N + c0] = make_float2(acc[mt][nt][2], acc[mt][nt][3]);
        }
    }
}

// ---------------------------------------------------------------------------
// YaRN RoPE applied in-place to Q and K inside g_qkv.
// ---------------------------------------------------------------------------
#define ATTN_FACTOR 1.4158883083359672f
#define LG2_BASE 19.931568569324174f   // log2(1e6)

__global__ void rope_kernel(float* __restrict__ qkv) {
    long long idx = (long long)blockIdx.x * blockDim.x + threadIdx.x;
    const long long total = (long long)MROWS * 20 * 64;
    if (idx >= total) return;

    int i   = (int)(idx & 63);
    int hd  = (int)((idx >> 6) % 20);
    long long bt = idx / (64 * 20);
    int t   = (int)(bt % Tsz);

    float fi = (float)i;
    float ramp = fminf(fmaxf((fi - 23.0f) * (1.0f / 8.0f), 0.0f), 1.0f);
    float extrap = 1.0f - ramp;
    float pf = exp2f(fi * (LG2_BASE / 64.0f));
    float inv = ramp * (1.0f / (64.0f * pf)) + extrap * (1.0f / pf);

    float angle = (float)t * inv;
    float c = cosf(angle);
    float s = sinf(angle);

    int col = (hd < 16) ? hd * DH : NE + (hd - 16) * DH;
    float* p = qkv + bt * QKV_W + col + 2 * i;
    float xe = p[0], xo = p[1];
    p[0] = (xe * c - xo * s) * ATTN_FACTOR;
    p[1] = (xe * s + xo * c) * ATTN_FACTOR;
}

// ---------------------------------------------------------------------------
// Flash attention (causal, GQA), tiled softmax.
// ---------------------------------------------------------------------------
#define AT_ROWS 64
#define AT_KT 32
#define SCALE_L2 (0.08838834764831843f * 1.4426950408889634f)   // (1/sqrt(128))*log2(e)

__global__ __launch_bounds__(256, 2)
void flash_attn_kernel(const float* __restrict__ qkv, float* __restrict__ y) {
    __shared__ float Ks[AT_KT][DH];
    __shared__ float Vs[AT_KT][DH];
    __shared__ float Ps[AT_ROWS][AT_KT + 1];

    const int qt = blockIdx.x;
    const int bh = blockIdx.y;
    const int b  = bh >> 4;
    const int hh = bh & 15;
    const int kvh = hh >> 2;

    const int tid = threadIdx.x;
    const int row = tid >> 2;          // 0..63
    const int qlane = tid & 3;         // 0..3
    const int qrow = qt * AT_ROWS + row;
    const int dbase = qlane * 32;

    const float* Qp = qkv + ((size_t)(b * Tsz + qrow)) * QKV_W + hh * DH + dbase;
    const float* Kbase = qkv + (size_t)b * Tsz * QKV_W + NE + kvh * DH;
    const float* Vbase = Kbase + NKV * DH;

    float q[32];
    #pragma unroll
    for (int d = 0; d < 32; d++) q[d] = Qp[d] * SCALE_L2;

    float acc[32];
    #pragma unroll
    for (int d = 0; d < 32; d++) acc[d] = 0.f;
    float m = -1e30f, l = 0.f;

    const int ntiles = (qt + 1) * (AT_ROWS / AT_KT);

    for (int t0 = 0; t0 < ntiles; t0++) {
        const int k0 = t0 * AT_KT;
        __syncthreads();
        #pragma unroll
        for (int i = tid; i < AT_KT * DH / 4; i += 256) {
            int r = i >> 5, c = (i & 31) * 4;
            *(float4*)&Ks[r][c] = *(const float4*)&Kbase[(size_t)(k0 + r) * QKV_W + c];
            *(float4*)&Vs[r][c] = *(const float4*)&Vbase[(size_t)(k0 + r) * QKV_W + c];
        }
        __syncthreads();

        float pl[8];
        float tmax = -1e30f;
        #pragma unroll
        for (int j = 0; j < AT_KT; j++) {
            const float4* kr = (const float4*)&Ks[j][dbase];
            float s = 0.f;
            #pragma unroll
            for (int d4 = 0; d4 < 8; d4++) {
                float4 kv = kr[d4];
                s += q[d4 * 4 + 0] * kv.x + q[d4 * 4 + 1] * kv.y
                   + q[d4 * 4 + 2] * kv.z + q[d4 * 4 + 3] * kv.w;
            }
            s += __shfl_xor_sync(0xffffffffu, s, 1);
            s += __shfl_xor_sync(0xffffffffu, s, 2);
            if (k0 + j > qrow) s = -1e30f;
            tmax = fmaxf(tmax, s);
            if ((j & 3) == qlane) pl[j >> 2] = s;
        }
        float m_new = fmaxf(m, tmax);
        float alpha = exp2f(m - m_new);
        float lsum = 0.f;
        #pragma unroll
        for (int jj = 0; jj < 8; jj++) {
            pl[jj] = exp2f(pl[jj] - m_new);
            lsum += pl[jj];
        }
        lsum += __shfl_xor_sync(0xffffffffu, lsum, 1);
        lsum += __shfl_xor_sync(0xffffffffu, lsum, 2);
        l = l * alpha + lsum;
        m = m_new;
        #pragma unroll
        for (int jj = 0; jj < 8; jj++) Ps[row][jj * 4 + qlane] = pl[jj];
        #pragma unroll
        for (int d = 0; d < 32; d++) acc[d] *= alpha;
        __syncthreads();

        #pragma unroll
        for (int j = 0; j < AT_KT; j++) {
            float pj = Ps[row][j];
            const float4* vr = (const float4*)&Vs[j][dbase];
            #pragma unroll
            for (int d4 = 0; d4 < 8; d4++) {
                float4 vv = vr[d4];
                acc[d4 * 4 + 0] += pj * vv.x;
                acc[d4 * 4 + 1] += pj * vv.y;
                acc[d4 * 4 + 2] += pj * vv.z;
                acc[d4 * 4 + 3] += pj * vv.w;
            }
        }
    }

    float inv_l = 1.0f / l;
    float* yp = y + ((size_t)(b * Tsz + qrow)) * NE + hh * DH + dbase;
    #pragma unroll
    for (int d4 = 0; d4 < 8; d4++) {
        *(float4*)(yp + d4 * 4) = make_float4(acc[d4 * 4 + 0] * inv_l, acc[d4 * 4 + 1] * inv_l,
                                              acc[d4 * 4 + 2] * inv_l, acc[d4 * 4 + 3] * inv_l);
    }
}

// ---------------------------------------------------------------------------
// Launch
// ---------------------------------------------------------------------------
extern "C" void kernel_launch(void* const* d_in, const int* in_sizes, int n_in,
                              void* d_out, int out_size) {
    const float* x     = (const float*)d_in[0];
    const float* w_qkv = (const float*)d_in[1];
    const float* w_o   = (const float*)d_in[2];
    float* out = (float*)d_out;

    float* qkv = nullptr;
    float* y   = nullptr;
    __nv_bfloat16 *ahi, *alo, *bhi, *blo;
    cudaGetSymbolAddress((void**)&qkv, g_qkv);
    cudaGetSymbolAddress((void**)&y,   g_y);
    cudaGetSymbolAddress((void**)&ahi, g_ahi);
    cudaGetSymbolAddress((void**)&alo, g_alo);
    cudaGetSymbolAddress((void**)&bhi, g_bhi);
    cudaGetSymbolAddress((void**)&blo, g_blo);

    cudaFuncSetAttribute(bgemm_mma, cudaFuncAttributeMaxDynamicSharedMemorySize, GEMM_SMEM_BYTES);

    // 1) Split x (activations) and w_qkv (transposed) to bf16 hi/lo
    {
        int n = MROWS * NE;
        split_kernel<<<(n + 255) / 256, 256>>>(x, ahi, alo, n);
        dim3 grid(QKV_W / 32, NE / 32);
        split_T_kernel<<<grid, dim3(32, 8)>>>(w_qkv, bhi, blo, NE, QKV_W);
    }

    // 2) QKV projection: [4096,2048] @ [2048,3072] -> g_qkv
    {
        dim3 grid(QKV_W / BN, MROWS / BM);
        bgemm_mma<<<grid, 256, GEMM_SMEM_BYTES>>>(ahi, alo, bhi, blo, qkv, QKV_W, NE);
    }

    // 3) RoPE on Q and K (in place, fp32)
    {
        long long total = (long long)MROWS * 20 * 64;
        rope_kernel<<<(int)((total + 255) / 256), 256>>>(qkv);
    }

    // 4) Causal GQA flash attention -> y [4096, 2048]
    {
        dim3 grid(Tsz / AT_ROWS, Bsz * NH);
        flash_attn_kernel<<<grid, 256>>>(qkv, y);
    }

    // 5) Split y and w_o, then output projection -> out
    {
        int n = MROWS * NE;
        split_kernel<<<(n + 255) / 256, 256>>>(y, ahi, alo, n);
        dim3 gridT(NE / 32, NE / 32);
        split_T_kernel<<<gridT, dim3(32, 8)>>>(w_o, bhi, blo, NE, NE);
        dim3 grid(NE / BN, MROWS / BM);
        bgemm_mma<<<grid, 256, GEMM_SMEM_BYTES>>>(ahi, alo, bhi, blo, out, NE, NE);
    }
}